// round 2
// baseline (speedup 1.0000x reference)
#include <cuda_runtime.h>

#define GG    4096
#define MM    50
#define KK    30
#define HH    32
#define FIN   128
#define EPG   400      // edges per graph
#define DLAT  97
#define DDENSE 352

// scratch for per-graph conv output (dense-layer input), static device memory (no allocs)
__device__ float g_z[GG * DDENSE];

struct Smem {
    // ---- float4-copied blocks first (all sizes multiple of 16B, 16B-aligned offsets) ----
    float xs[MM * FIN];      // 25600 B : x tile; reused as h buffer [50][32] for layers 2-4
    float W0s[FIN * HH];     // 16384
    float W1s[HH * HH];      // 4096
    float W2s[HH * HH];      // 4096
    float W3s[HH];           // 128
    float C1ws[16 * DLAT];   // 6208
    float C2ws[32 * 16 * 5]; // 10240
    // ---- scalar-access blocks ----
    float lat[MM * DLAT];    // 19400 : concat[h1,h2,h3,h4]
    float tmp[MM * HH];      // 6400  : h @ W (pre-aggregation)
    float2 epack[EPG];       // 3200  : (src_local_bits, norm) grouped by dst (CSR)
    float z1[16 * KK];       // 1920
    float pooled[16 * 15];   // 960
    float dinv[MM];
    float h4v[MM];
    int   rp[MM + 1];
    int   cnt[MM];
    int   sel[KK];
    int   eraws[EPG];
    int   erawd[EPG];
};

__device__ __forceinline__ void cp4(float* dst, const float* __restrict__ src,
                                    int n4, int tid, int nt) {
    const float4* s = reinterpret_cast<const float4*>(src);
    float4* d = reinterpret_cast<float4*>(dst);
    for (int i = tid; i < n4; i += nt) d[i] = s[i];
}

// h[M, KD] @ W[KD, 32] -> tmp[M, 32].  Warp tile: 7 nodes x 32 channels,
// k-unrolled by 4 with float4 loads of h (11 LDS per 28 FMA).
template <int KD>
__device__ __forceinline__ void gcn_matmul(const float* __restrict__ in,
                                           const float* __restrict__ W,
                                           float* __restrict__ tmp,
                                           int warp, int lane) {
    int nbase = warp * 7;
    if (nbase >= MM) return;
    int ncnt = MM - nbase; if (ncnt > 7) ncnt = 7;
    float acc[7] = {0.f, 0.f, 0.f, 0.f, 0.f, 0.f, 0.f};
#pragma unroll 4
    for (int k = 0; k < KD; k += 4) {
        float wa = W[(k + 0) * HH + lane];
        float wb = W[(k + 1) * HH + lane];
        float wc = W[(k + 2) * HH + lane];
        float wd = W[(k + 3) * HH + lane];
#pragma unroll
        for (int j = 0; j < 7; j++) {
            if (j < ncnt) {
                float4 xv = *reinterpret_cast<const float4*>(&in[(nbase + j) * KD + k]);
                acc[j] = fmaf(xv.x, wa, fmaf(xv.y, wb, fmaf(xv.z, wc, fmaf(xv.w, wd, acc[j]))));
            }
        }
    }
    for (int j = 0; j < ncnt; j++) tmp[(nbase + j) * HH + lane] = acc[j];
}

// gather-aggregate (CSR by dst) + self loop + bias + tanh.
// writes result to lat[:, coloff:coloff+32] and to hbuf (= s.xs) for the next layer.
__device__ __forceinline__ void gcn_agg(Smem& s, int coloff, float bias,
                                        int warp, int lane) {
    for (int n = warp; n < MM; n += 8) {
        float di = s.dinv[n];
        float a = s.tmp[n * HH + lane] * di * di;
        int e1 = s.rp[n + 1];
        for (int e = s.rp[n]; e < e1; e++) {
            float2 p = s.epack[e];
            a = fmaf(s.tmp[__float_as_int(p.x) * HH + lane], p.y, a);
        }
        float r = tanhf(a + bias);
        s.lat[n * DLAT + coloff + lane] = r;
        s.xs[n * HH + lane] = r;
    }
}

__global__ void __launch_bounds__(256)
graph_kernel(const float* __restrict__ x, const int* __restrict__ ei,
             const float* __restrict__ W0, const float* __restrict__ b0,
             const float* __restrict__ W1, const float* __restrict__ b1,
             const float* __restrict__ W2, const float* __restrict__ b2,
             const float* __restrict__ W3, const float* __restrict__ b3,
             const float* __restrict__ C1w, const float* __restrict__ C1b,
             const float* __restrict__ C2w, const float* __restrict__ C2b,
             int E) {
    extern __shared__ char raw[];
    Smem& s = *reinterpret_cast<Smem*>(raw);
    const int tid = threadIdx.x, lane = tid & 31, warp = tid >> 5;
    const int g = blockIdx.x;

    // ---- stage weights + x tile into smem ----
    cp4(s.xs, x + (size_t)g * MM * FIN, MM * FIN / 4, tid, 256);
    cp4(s.W0s, W0, FIN * HH / 4, tid, 256);
    cp4(s.W1s, W1, HH * HH / 4, tid, 256);
    cp4(s.W2s, W2, HH * HH / 4, tid, 256);
    cp4(s.W3s, W3, HH / 4, tid, 256);
    cp4(s.C1ws, C1w, 16 * DLAT / 4, tid, 256);
    cp4(s.C2ws, C2w, 32 * 16 * 5 / 4, tid, 256);

    if (tid < MM) s.cnt[tid] = 1;  // self loop
    const int ebase = g * EPG;
    for (int e = tid; e < EPG; e += 256) {
        s.eraws[e] = ei[ebase + e] - g * MM;
        s.erawd[e] = ei[E + ebase + e] - g * MM;
    }
    __syncthreads();

    // ---- degree count (in-degree over dst + self loop) ----
    for (int e = tid; e < EPG; e += 256) atomicAdd(&s.cnt[s.erawd[e]], 1);
    __syncthreads();

    if (tid < MM) s.dinv[tid] = rsqrtf((float)s.cnt[tid]);
    if (tid == 0) {
        int acc = 0;
        for (int n = 0; n < MM; n++) { s.rp[n] = acc; acc += s.cnt[n] - 1; }
        s.rp[MM] = acc;  // == EPG
    }
    __syncthreads();
    if (tid < MM) s.cnt[tid] = 0;
    __syncthreads();

    // ---- build CSR grouped by dst: (src_local, norm) ----
    for (int e = tid; e < EPG; e += 256) {
        int d = s.erawd[e], sl = s.eraws[e];
        int pos = s.rp[d] + atomicAdd(&s.cnt[d], 1);
        s.epack[pos] = make_float2(__int_as_float(sl), s.dinv[sl] * s.dinv[d]);
    }
    __syncthreads();

    // ---- GCN layers 1-3 ----
    gcn_matmul<FIN>(s.xs, s.W0s, s.tmp, warp, lane);
    __syncthreads();
    gcn_agg(s, 0, __ldg(&b0[lane]), warp, lane);
    __syncthreads();

    gcn_matmul<HH>(s.xs, s.W1s, s.tmp, warp, lane);
    __syncthreads();
    gcn_agg(s, 32, __ldg(&b1[lane]), warp, lane);
    __syncthreads();

    gcn_matmul<HH>(s.xs, s.W2s, s.tmp, warp, lane);
    __syncthreads();
    gcn_agg(s, 64, __ldg(&b2[lane]), warp, lane);
    __syncthreads();

    // ---- layer 4: H=32 -> 1 ----
    for (int n = warp; n < MM; n += 8) {
        float v = s.xs[n * HH + lane] * s.W3s[lane];
#pragma unroll
        for (int o = 16; o; o >>= 1) v += __shfl_xor_sync(0xffffffffu, v, o);
        if (lane == 0) s.tmp[n] = v;
    }
    __syncthreads();
    if (tid < MM) {
        int n = tid;
        float di = s.dinv[n];
        float a = s.tmp[n] * di * di;
        int e1 = s.rp[n + 1];
        for (int e = s.rp[n]; e < e1; e++) {
            float2 p = s.epack[e];
            a = fmaf(s.tmp[__float_as_int(p.x)], p.y, a);
        }
        float r = tanhf(a + __ldg(&b3[0]));
        s.lat[n * DLAT + 96] = r;
        s.h4v[n] = r;
    }
    __syncthreads();

    // ---- sort-pool: exact rank == stable argsort(-h4) ----
    if (tid < MM) {
        float vi = s.h4v[tid];
        int r = 0;
        for (int j = 0; j < MM; j++) {
            float vj = s.h4v[j];
            r += (vj > vi) || (vj == vi && j < tid);
        }
        if (r < KK) s.sel[r] = tid;
    }
    __syncthreads();

    // ---- conv1 (per-slot 97-dot) + relu ----
    for (int o = tid; o < 16 * KK; o += 256) {
        int t = o % KK, c = o / KK;
        const float* lr = &s.lat[s.sel[t] * DLAT];
        const float* cw = &s.C1ws[c * DLAT];
        float a = __ldg(&C1b[c]);
#pragma unroll 4
        for (int d = 0; d < DLAT; d++) a = fmaf(lr[d], cw[d], a);
        s.z1[c * KK + t] = fmaxf(a, 0.f);
    }
    __syncthreads();

    // ---- maxpool(2,2) ----
    if (tid < 16 * 15) {
        int u = tid % 15, c = tid / 15;
        s.pooled[c * 15 + u] = fmaxf(s.z1[c * KK + 2 * u], s.z1[c * KK + 2 * u + 1]);
    }
    __syncthreads();

    // ---- conv2 (16->32, k=5) + relu -> global scratch [g][o*11+u] ----
    for (int o2 = tid; o2 < DDENSE; o2 += 256) {
        int o = o2 / 11, u = o2 % 11;
        float a = __ldg(&C2b[o]);
#pragma unroll
        for (int i = 0; i < 16; i++) {
            const float* pw = &s.C2ws[(o * 16 + i) * 5];
            const float* pp = &s.pooled[i * 15 + u];
#pragma unroll
            for (int k2 = 0; k2 < 5; k2++) a = fmaf(pp[k2], pw[k2], a);
        }
        g_z[(size_t)g * DDENSE + o2] = fmaxf(a, 0.f);
    }
}

// Fused dense: relu(z @ L1w + L1b) @ L2w + L2b, 32 graphs per CTA.
// Warp tile: 32 channels (lane) x 16 graphs (registers) -> 0.25 LDS / FMA.
__global__ void __launch_bounds__(256)
dense_kernel(const float* __restrict__ L1w, const float* __restrict__ L1b,
             const float* __restrict__ L2w, const float* __restrict__ L2b,
             float* __restrict__ out) {
    __shared__ float zs[32][DDENSE];
    __shared__ float red[8][16];
    const int tid = threadIdx.x, lane = tid & 31, warp = tid >> 5;
    const int gbase = blockIdx.x * 32;

    // load 32 graphs x 352
    {
        const float4* zsrc = reinterpret_cast<const float4*>(&g_z[(size_t)gbase * DDENSE]);
        float4* zdst = reinterpret_cast<float4*>(&zs[0][0]);
        for (int i = tid; i < 32 * DDENSE / 4; i += 256) zdst[i] = zsrc[i];
    }
    __syncthreads();

    const int cb = warp & 3;   // channel block (4 x 32 = 128 channels)
    const int gg = warp >> 2;  // graph half (2 x 16 graphs)
    const int ch = cb * 32 + lane;
    const float* zrow0 = &zs[gg * 16][0];

    float acc[16];
    float l1b = __ldg(&L1b[ch]);
#pragma unroll
    for (int j = 0; j < 16; j++) acc[j] = l1b;

#pragma unroll 2
    for (int d = 0; d < DDENSE; d += 4) {
        float w0 = __ldg(&L1w[(d + 0) * 128 + ch]);
        float w1 = __ldg(&L1w[(d + 1) * 128 + ch]);
        float w2 = __ldg(&L1w[(d + 2) * 128 + ch]);
        float w3 = __ldg(&L1w[(d + 3) * 128 + ch]);
#pragma unroll
        for (int j = 0; j < 16; j++) {
            float4 zv = *reinterpret_cast<const float4*>(&zrow0[j * DDENSE + d]);
            acc[j] = fmaf(zv.x, w0, fmaf(zv.y, w1, fmaf(zv.z, w2, fmaf(zv.w, w3, acc[j]))));
        }
    }

    float w2v = __ldg(&L2w[ch]);
#pragma unroll
    for (int j = 0; j < 16; j++) {
        float p = fmaxf(acc[j], 0.f) * w2v;
#pragma unroll
        for (int o = 16; o; o >>= 1) p += __shfl_xor_sync(0xffffffffu, p, o);
        if (lane == 0) red[warp][j] = p;
    }
    __syncthreads();

    if (tid < 32) {
        int ggi = tid >> 4, j = tid & 15;
        float sum = red[ggi * 4 + 0][j] + red[ggi * 4 + 1][j] +
                    red[ggi * 4 + 2][j] + red[ggi * 4 + 3][j] + __ldg(&L2b[0]);
        out[gbase + ggi * 16 + j] = sum;
    }
}

extern "C" void kernel_launch(void* const* d_in, const int* in_sizes, int n_in,
                              void* d_out, int out_size) {
    const float* x   = (const float*)d_in[0];
    const int*   ei  = (const int*)d_in[1];
    // d_in[2] = batch (unused; graphs are contiguous equal-size blocks)
    const float* W0  = (const float*)d_in[3];
    const float* b0  = (const float*)d_in[4];
    const float* W1  = (const float*)d_in[5];
    const float* b1  = (const float*)d_in[6];
    const float* W2  = (const float*)d_in[7];
    const float* b2  = (const float*)d_in[8];
    const float* W3  = (const float*)d_in[9];
    const float* b3  = (const float*)d_in[10];
    const float* C1w = (const float*)d_in[11];
    const float* C1b = (const float*)d_in[12];
    const float* C2w = (const float*)d_in[13];
    const float* C2b = (const float*)d_in[14];
    const float* L1w = (const float*)d_in[15];
    const float* L1b = (const float*)d_in[16];
    const float* L2w = (const float*)d_in[17];
    const float* L2b = (const float*)d_in[18];

    const int E = in_sizes[1] / 2;
    const int smem = (int)sizeof(Smem);
    cudaFuncSetAttribute(graph_kernel, cudaFuncAttributeMaxDynamicSharedMemorySize, smem);

    graph_kernel<<<GG, 256, smem>>>(x, ei, W0, b0, W1, b1, W2, b2, W3, b3,
                                    C1w, C1b, C2w, C2b, E);
    dense_kernel<<<GG / 32, 256>>>(L1w, L1b, L2w, L2b, (float*)d_out);
}

// round 3
// speedup vs baseline: 1.2030x; 1.2030x over previous
#include <cuda_runtime.h>

#define GG    4096
#define MM    50
#define KK    30
#define HH    32
#define FIN   128
#define EPG   400      // edges per graph
#define DLAT  97
#define DDENSE 352

// scratch for per-graph conv output (dense-layer input)
__device__ float g_z[GG * DDENSE];

struct Smem {
    float  xs[MM * FIN];     // 25600 B : x tile; reused as h buffer [50][32] for layers 2-4
    float  lat[MM * DLAT];   // 19400 : concat[h1,h2,h3,h4]
    float  tmp[MM * HH];     // 6400  : h @ W (pre-aggregation)
    float2 epack[EPG];       // 3200  : (src_local_bits, norm) grouped by dst (CSR)
    float  z1[16 * KK];      // 1920
    float  pooled[16 * 15];  // 960
    float  dinv[MM];
    float  h4v[MM];
    int    rp[MM + 1];
    int    cnt[MM];          // degree counter (init 1 = self loop)
    int    cnt2[MM];         // scatter cursor (init 0)
    int    sel[KK];
    int    eraws[EPG];
    int    erawd[EPG];
};

// h[M, KD](smem) @ W[KD, 32](global, L1-hot) -> tmp[M, 32].
// Warp tile: 7 nodes x 32 channels. x loads are 16B smem broadcasts.
template <int KD>
__device__ __forceinline__ void gcn_matmul(const float* __restrict__ in,
                                           const float* __restrict__ Wg,
                                           float* __restrict__ tmp,
                                           int warp, int lane) {
    int nbase = warp * 7;
    if (nbase >= MM) return;
    int ncnt = MM - nbase; if (ncnt > 7) ncnt = 7;
    float acc[7] = {0.f, 0.f, 0.f, 0.f, 0.f, 0.f, 0.f};
#pragma unroll 4
    for (int k = 0; k < KD; k += 4) {
        float wa = __ldg(&Wg[(k + 0) * HH + lane]);
        float wb = __ldg(&Wg[(k + 1) * HH + lane]);
        float wc = __ldg(&Wg[(k + 2) * HH + lane]);
        float wd = __ldg(&Wg[(k + 3) * HH + lane]);
#pragma unroll
        for (int j = 0; j < 7; j++) {
            if (j < ncnt) {
                float4 xv = *reinterpret_cast<const float4*>(&in[(nbase + j) * KD + k]);
                acc[j] = fmaf(xv.x, wa, fmaf(xv.y, wb, fmaf(xv.z, wc, fmaf(xv.w, wd, acc[j]))));
            }
        }
    }
    for (int j = 0; j < ncnt; j++) tmp[(nbase + j) * HH + lane] = acc[j];
}

// gather-aggregate (CSR by dst) + self loop + bias + tanh.
__device__ __forceinline__ void gcn_agg(Smem& s, int coloff, float bias,
                                        int warp, int lane) {
    for (int n = warp; n < MM; n += 8) {
        float di = s.dinv[n];
        float a = s.tmp[n * HH + lane] * di * di;
        int e1 = s.rp[n + 1];
        for (int e = s.rp[n]; e < e1; e++) {
            float2 p = s.epack[e];
            a = fmaf(s.tmp[__float_as_int(p.x) * HH + lane], p.y, a);
        }
        float r = tanhf(a + bias);
        s.lat[n * DLAT + coloff + lane] = r;
        s.xs[n * HH + lane] = r;
    }
}

__global__ void __launch_bounds__(256, 3)
graph_kernel(const float* __restrict__ x, const int* __restrict__ ei,
             const float* __restrict__ W0, const float* __restrict__ b0,
             const float* __restrict__ W1, const float* __restrict__ b1,
             const float* __restrict__ W2, const float* __restrict__ b2,
             const float* __restrict__ W3, const float* __restrict__ b3,
             const float* __restrict__ C1w, const float* __restrict__ C1b,
             const float* __restrict__ C2w, const float* __restrict__ C2b,
             int E) {
    extern __shared__ char raw[];
    Smem& s = *reinterpret_cast<Smem*>(raw);
    const int tid = threadIdx.x, lane = tid & 31, warp = tid >> 5;
    const int g = blockIdx.x;

    // ---- stage x tile (coalesced), read edges, init counters ----
    {
        const float4* xsrc = reinterpret_cast<const float4*>(x + (size_t)g * MM * FIN);
        float4* xdst = reinterpret_cast<float4*>(s.xs);
        for (int i = tid; i < MM * FIN / 4; i += 256) xdst[i] = xsrc[i];
    }
    if (tid < MM) { s.cnt[tid] = 1; s.cnt2[tid] = 0; }  // self loop in cnt
    const int ebase = g * EPG;
    for (int e = tid; e < EPG; e += 256) {
        s.eraws[e] = ei[ebase + e] - g * MM;
        s.erawd[e] = ei[E + ebase + e] - g * MM;
    }
    __syncthreads();

    // ---- degree count ----
    for (int e = tid; e < EPG; e += 256) atomicAdd(&s.cnt[s.erawd[e]], 1);
    __syncthreads();

    // ---- dinv + warp-parallel exclusive scan of (cnt-1) -> rp ----
    if (tid >= 64 && tid < 64 + MM) s.dinv[tid - 64] = rsqrtf((float)s.cnt[tid - 64]);
    if (warp == 0) {
        int a = (lane < MM) ? (s.cnt[lane] - 1) : 0;
        int b = (lane + 32 < MM) ? (s.cnt[lane + 32] - 1) : 0;
        int sa = a, sb = b;
#pragma unroll
        for (int o = 1; o < 32; o <<= 1) {
            int ta = __shfl_up_sync(0xffffffffu, sa, o);
            int tb = __shfl_up_sync(0xffffffffu, sb, o);
            if (lane >= o) { sa += ta; sb += tb; }
        }
        int tot_a = __shfl_sync(0xffffffffu, sa, 31);
        s.rp[lane] = sa - a;                       // exclusive, nodes 0..31
        if (lane + 32 < MM) s.rp[lane + 32] = tot_a + sb - b;
        if (lane == 31) s.rp[MM] = tot_a + sb;     // sb@31 = total of upper half
    }
    __syncthreads();

    // ---- build CSR grouped by dst: (src_local, norm) ----
    for (int e = tid; e < EPG; e += 256) {
        int d = s.erawd[e], sl = s.eraws[e];
        int pos = s.rp[d] + atomicAdd(&s.cnt2[d], 1);
        s.epack[pos] = make_float2(__int_as_float(sl), s.dinv[sl] * s.dinv[d]);
    }
    __syncthreads();

    // ---- GCN layers 1-3 (weights straight from global; L1-hot across CTAs) ----
    gcn_matmul<FIN>(s.xs, W0, s.tmp, warp, lane);
    __syncthreads();
    gcn_agg(s, 0, __ldg(&b0[lane]), warp, lane);
    __syncthreads();

    gcn_matmul<HH>(s.xs, W1, s.tmp, warp, lane);
    __syncthreads();
    gcn_agg(s, 32, __ldg(&b1[lane]), warp, lane);
    __syncthreads();

    gcn_matmul<HH>(s.xs, W2, s.tmp, warp, lane);
    __syncthreads();
    gcn_agg(s, 64, __ldg(&b2[lane]), warp, lane);
    __syncthreads();

    // ---- layer 4: H=32 -> 1 ----
    {
        float w3 = __ldg(&W3[lane]);
        for (int n = warp; n < MM; n += 8) {
            float v = s.xs[n * HH + lane] * w3;
#pragma unroll
            for (int o = 16; o; o >>= 1) v += __shfl_xor_sync(0xffffffffu, v, o);
            if (lane == 0) s.tmp[n] = v;
        }
    }
    __syncthreads();
    if (tid < MM) {
        int n = tid;
        float di = s.dinv[n];
        float a = s.tmp[n] * di * di;
        int e1 = s.rp[n + 1];
        for (int e = s.rp[n]; e < e1; e++) {
            float2 p = s.epack[e];
            a = fmaf(s.tmp[__float_as_int(p.x)], p.y, a);
        }
        float r = tanhf(a + __ldg(&b3[0]));
        s.lat[n * DLAT + 96] = r;
        s.h4v[n] = r;
    }
    __syncthreads();

    // ---- sort-pool: exact rank == stable argsort(-h4) ----
    if (tid < MM) {
        float vi = s.h4v[tid];
        int r = 0;
        for (int j = 0; j < MM; j++) {
            float vj = s.h4v[j];
            r += (vj > vi) || (vj == vi && j < tid);
        }
        if (r < KK) s.sel[r] = tid;
    }
    __syncthreads();

    // ---- conv1 (per-slot 97-dot) + relu ----
    for (int o = tid; o < 16 * KK; o += 256) {
        int t = o % KK, c = o / KK;
        const float* lr = &s.lat[s.sel[t] * DLAT];
        const float* cw = &C1w[c * DLAT];
        float a = __ldg(&C1b[c]);
#pragma unroll 4
        for (int d = 0; d < DLAT; d++) a = fmaf(lr[d], __ldg(&cw[d]), a);
        s.z1[c * KK + t] = fmaxf(a, 0.f);
    }
    __syncthreads();

    // ---- maxpool(2,2) ----
    if (tid < 16 * 15) {
        int u = tid % 15, c = tid / 15;
        s.pooled[c * 15 + u] = fmaxf(s.z1[c * KK + 2 * u], s.z1[c * KK + 2 * u + 1]);
    }
    __syncthreads();

    // ---- conv2 (16->32, k=5) + relu -> global scratch ----
    for (int o2 = tid; o2 < DDENSE; o2 += 256) {
        int o = o2 / 11, u = o2 % 11;
        float a = __ldg(&C2b[o]);
#pragma unroll
        for (int i = 0; i < 16; i++) {
            const float* pw = &C2w[(o * 16 + i) * 5];
            const float* pp = &s.pooled[i * 15 + u];
#pragma unroll
            for (int k2 = 0; k2 < 5; k2++) a = fmaf(pp[k2], __ldg(&pw[k2]), a);
        }
        g_z[(size_t)g * DDENSE + o2] = fmaxf(a, 0.f);
    }
}

// Fused dense: relu(z @ L1w + L1b) @ L2w + L2b. 8 graphs / CTA, grid 512.
__global__ void __launch_bounds__(256)
dense_kernel(const float* __restrict__ L1w, const float* __restrict__ L1b,
             const float* __restrict__ L2w, const float* __restrict__ L2b,
             float* __restrict__ out) {
    __shared__ float zs[8][DDENSE];
    __shared__ float red[8][4];
    const int tid = threadIdx.x, lane = tid & 31, warp = tid >> 5;
    const int gbase = blockIdx.x * 8;

    {
        const float4* zsrc = reinterpret_cast<const float4*>(&g_z[(size_t)gbase * DDENSE]);
        float4* zdst = reinterpret_cast<float4*>(&zs[0][0]);
        for (int i = tid; i < 8 * DDENSE / 4; i += 256) zdst[i] = zsrc[i];
    }
    __syncthreads();

    const int cb = warp & 3;   // channel block (4 x 32 = 128 channels)
    const int gg = warp >> 2;  // graph group (2 x 4 graphs)
    const int ch = cb * 32 + lane;
    const float* zrow0 = &zs[gg * 4][0];

    float acc[4];
    float l1b = __ldg(&L1b[ch]);
#pragma unroll
    for (int j = 0; j < 4; j++) acc[j] = l1b;

#pragma unroll 4
    for (int d = 0; d < DDENSE; d += 4) {
        float w0 = __ldg(&L1w[(d + 0) * 128 + ch]);
        float w1 = __ldg(&L1w[(d + 1) * 128 + ch]);
        float w2 = __ldg(&L1w[(d + 2) * 128 + ch]);
        float w3 = __ldg(&L1w[(d + 3) * 128 + ch]);
#pragma unroll
        for (int j = 0; j < 4; j++) {
            float4 zv = *reinterpret_cast<const float4*>(&zrow0[j * DDENSE + d]);
            acc[j] = fmaf(zv.x, w0, fmaf(zv.y, w1, fmaf(zv.z, w2, fmaf(zv.w, w3, acc[j]))));
        }
    }

    float w2v = __ldg(&L2w[ch]);
#pragma unroll
    for (int j = 0; j < 4; j++) {
        float p = fmaxf(acc[j], 0.f) * w2v;
#pragma unroll
        for (int o = 16; o; o >>= 1) p += __shfl_xor_sync(0xffffffffu, p, o);
        if (lane == 0) red[warp][j] = p;
    }
    __syncthreads();

    if (tid < 8) {
        int ggi = tid >> 2, j = tid & 3;
        float sum = red[ggi * 4 + 0][j] + red[ggi * 4 + 1][j] +
                    red[ggi * 4 + 2][j] + red[ggi * 4 + 3][j] + __ldg(&L2b[0]);
        out[gbase + ggi * 4 + j] = sum;
    }
}

extern "C" void kernel_launch(void* const* d_in, const int* in_sizes, int n_in,
                              void* d_out, int out_size) {
    const float* x   = (const float*)d_in[0];
    const int*   ei  = (const int*)d_in[1];
    // d_in[2] = batch (unused; graphs are contiguous equal-size blocks)
    const float* W0  = (const float*)d_in[3];
    const float* b0  = (const float*)d_in[4];
    const float* W1  = (const float*)d_in[5];
    const float* b1  = (const float*)d_in[6];
    const float* W2  = (const float*)d_in[7];
    const float* b2  = (const float*)d_in[8];
    const float* W3  = (const float*)d_in[9];
    const float* b3  = (const float*)d_in[10];
    const float* C1w = (const float*)d_in[11];
    const float* C1b = (const float*)d_in[12];
    const float* C2w = (const float*)d_in[13];
    const float* C2b = (const float*)d_in[14];
    const float* L1w = (const float*)d_in[15];
    const float* L1b = (const float*)d_in[16];
    const float* L2w = (const float*)d_in[17];
    const float* L2b = (const float*)d_in[18];

    const int E = in_sizes[1] / 2;
    const int smem = (int)sizeof(Smem);
    cudaFuncSetAttribute(graph_kernel, cudaFuncAttributeMaxDynamicSharedMemorySize, smem);

    graph_kernel<<<GG, 256, smem>>>(x, ei, W0, b0, W1, b1, W2, b2, W3, b3,
                                    C1w, C1b, C2w, C2b, E);
    dense_kernel<<<GG / 8, 256>>>(L1w, L1b, L2w, L2b, (float*)d_out);
}